// round 16
// baseline (speedup 1.0000x reference)
#include <cuda_runtime.h>
#include <cuda_bf16.h>
#include <cuda_fp16.h>
#include <math.h>
#include <stdint.h>

#define B_   4
#define C_   256
#define D_   128
#define HW_  16384
#define W_   128
#define T_   16384
#define MAX_DELTA 0.0009765625f   // 0.5/512

__device__ uint8_t g_vm8[(size_t)B_ * HW_ * D_];       // fp8 vm [b][pix][d]
__device__ uint8_t g_vmB8[(size_t)B_ * HW_ * D_];      // fp8 3x3 box-summed vm
__device__ __half g_feat[(size_t)B_ * T_ * D_];        // fp16 feat [pt][d]
__device__ __nv_bfloat16 g_wp[D_ * C_];                // bf16 Wp [d][c]
__device__ __half g_w1h[D_ * D_];                      // fp16 W1 [j][k]

// ---------------------------------------------------------------------------
__device__ __forceinline__ uint32_t s2u(const void* p) {
    return (uint32_t)__cvta_generic_to_shared(p);
}
__device__ __forceinline__ void cp_async16(void* smem_dst, const void* gmem_src) {
    asm volatile("cp.async.cg.shared.global [%0], [%1], 16;\n"
        :: "r"(s2u(smem_dst)), "l"(gmem_src));
}
__device__ __forceinline__ void mbar_init(uint32_t addr, uint32_t cnt) {
    asm volatile("mbarrier.init.shared.b64 [%0], %1;" :: "r"(addr), "r"(cnt) : "memory");
}
__device__ __forceinline__ void mbar_expect_tx(uint32_t addr, uint32_t bytes) {
    asm volatile("mbarrier.arrive.expect_tx.shared.b64 _, [%0], %1;"
        :: "r"(addr), "r"(bytes) : "memory");
}
__device__ __forceinline__ void bulk_g2s(uint32_t dst, const void* src,
                                         uint32_t bytes, uint32_t mbar) {
    asm volatile("cp.async.bulk.shared::cta.global.mbarrier::complete_tx::bytes "
        "[%0], [%1], %2, [%3];"
        :: "r"(dst), "l"(src), "r"(bytes), "r"(mbar) : "memory");
}
__device__ __forceinline__ void mbar_wait(uint32_t mbar, uint32_t parity) {
    uint32_t done;
    do {
        asm volatile("{\n\t.reg .pred p;\n\t"
            "mbarrier.try_wait.parity.acquire.cta.shared::cta.b64 p, [%1], %2;\n\t"
            "selp.b32 %0, 1, 0, p;\n\t}"
            : "=r"(done) : "r"(mbar), "r"(parity) : "memory");
    } while (!done);
}
__device__ __forceinline__ void fence_pa() {
    asm volatile("fence.proxy.async.shared::cta;" ::: "memory");
}
__device__ __forceinline__ void ldm_x4(uint32_t r[4], uint32_t addr) {
    asm volatile("ldmatrix.sync.aligned.m8n8.x4.shared.b16 {%0,%1,%2,%3}, [%4];\n"
        : "=r"(r[0]), "=r"(r[1]), "=r"(r[2]), "=r"(r[3]) : "r"(addr));
}
__device__ __forceinline__ void mma_bf16(float c[4], const uint32_t a[4], const uint32_t b[2]) {
    asm volatile("mma.sync.aligned.m16n8k16.row.col.f32.bf16.bf16.f32 "
        "{%0,%1,%2,%3}, {%4,%5,%6,%7}, {%8,%9}, {%0,%1,%2,%3};\n"
        : "+f"(c[0]), "+f"(c[1]), "+f"(c[2]), "+f"(c[3])
        : "r"(a[0]), "r"(a[1]), "r"(a[2]), "r"(a[3]), "r"(b[0]), "r"(b[1]));
}
__device__ __forceinline__ void mma_f16(float c[4], const uint32_t a[4], const uint32_t b[2]) {
    asm volatile("mma.sync.aligned.m16n8k16.row.col.f32.f16.f16.f32 "
        "{%0,%1,%2,%3}, {%4,%5,%6,%7}, {%8,%9}, {%0,%1,%2,%3};\n"
        : "+f"(c[0]), "+f"(c[1]), "+f"(c[2]), "+f"(c[3])
        : "r"(a[0]), "r"(a[1]), "r"(a[2]), "r"(a[3]), "r"(b[0]), "r"(b[1]));
}
__device__ __forceinline__ uint16_t pack_e4m3x2(float lo, float hi) {
    uint16_t r;
    asm("cvt.rn.satfinite.e4m3x2.f32 %0, %1, %2;" : "=h"(r) : "f"(hi), "f"(lo));
    return r;
}
__device__ __forceinline__ __half2 e4m3x2_to_h2(uint32_t u) {
    uint32_t r;
    asm("cvt.rn.f16x2.e4m3x2 %0, %1;" : "=r"(r) : "h"((uint16_t)u));
    return *(__half2*)&r;
}
__device__ __forceinline__ uint16_t h2_to_e4m3x2(__half2 h) {
    uint16_t r;
    asm("cvt.rn.satfinite.e4m3x2.f16x2 %0, %1;" : "=h"(r) : "r"(*(uint32_t*)&h));
    return r;
}
__device__ __forceinline__ uint32_t pack_bf16x2(float lo, float hi) {
    __nv_bfloat162 p = __floats2bfloat162_rn(lo, hi);
    return *(uint32_t*)&p;
}

// smem layout constants for proj
#define BSTR 264
#define BS_ELEMS  (128 * BSTR)
#define AS32STR 132
#define STAGE_ELEMS (32 * AS32STR)
#define PROJ_BAR_OFF (BS_ELEMS * 2 + 2 * STAGE_ELEMS * 4)   // 101376
#define PROJ_SMEM (PROJ_BAR_OFF + 64)                        // 101440 B

// ---------------------------------------------------------------------------
// Kernel 0: one-time weight conversion.
// ---------------------------------------------------------------------------
__global__ __launch_bounds__(256) void wt_convert(const float* __restrict__ Wp,
                                                  const float* __restrict__ W1)
{
    int i = blockIdx.x * 256 + threadIdx.x;
    if (i < 8192) {
        float4 v = *(const float4*)&Wp[i * 4];
        __nv_bfloat162* dst = (__nv_bfloat162*)&g_wp[i * 4];
        dst[0] = __floats2bfloat162_rn(v.x, v.y);
        dst[1] = __floats2bfloat162_rn(v.z, v.w);
    } else {
        int j = i - 8192;
        float4 v = *(const float4*)&W1[j * 4];
        __half2* dst = (__half2*)&g_w1h[j * 4];
        dst[0] = __floats2half2_rn(v.x, v.y);
        dst[1] = __floats2half2_rn(v.z, v.w);
    }
}

// ---------------------------------------------------------------------------
// Kernel 1: projection GEMM -> fp8 vm (R12 bulk version).
// ---------------------------------------------------------------------------
__global__ __launch_bounds__(256, 2) void proj_kernel(const float* __restrict__ fmap)
{
    extern __shared__ __align__(16) char smraw[];
    __nv_bfloat16* Bs = (__nv_bfloat16*)smraw;
    float*        As32 = (float*)(smraw + BS_ELEMS * 2);
    const uint32_t barB = s2u(smraw + PROJ_BAR_OFF);

    const int b    = blockIdx.y;
    const int tid  = threadIdx.x;
    const int lane = tid & 31, warp = tid >> 5;

    const float* fb = fmap + (size_t)b * C_ * HW_ + blockIdx.x * 256;

    if (tid == 0) {
        mbar_init(barB, 1); mbar_init(barB + 8, 1); mbar_init(barB + 16, 1);
        fence_pa();
    }
    __syncthreads();
    if (tid == 0) {
        mbar_expect_tx(barB + 16, 65536);
        mbar_expect_tx(barB,      16384);
        mbar_expect_tx(barB + 8,  16384);
    }
    __syncthreads();

    if (lane == 0) {
#pragma unroll
        for (int r = 0; r < 16; r++) {
            int row = warp * 16 + r;
            bulk_g2s(s2u(&Bs[row * BSTR]), g_wp + row * C_, 512, barB + 16);
        }
        if (warp == 0) {
#pragma unroll
            for (int r = 0; r < 32; r++)
                bulk_g2s(s2u(As32 + r * AS32STR), fb + (size_t)r * HW_, 512, barB);
        }
        if (warp == 1) {
            const float* src = fb + (size_t)32 * HW_;
#pragma unroll
            for (int r = 0; r < 32; r++)
                bulk_g2s(s2u(As32 + STAGE_ELEMS + r * AS32STR),
                         src + (size_t)r * HW_, 512, barB + 8);
        }
    }

    const int wm = (warp & 3) * 32;
    const int wn = (warp >> 2) * 64;
    const uint32_t bbase = s2u(Bs);

    float acc[2][8][4];
#pragma unroll
    for (int mt = 0; mt < 2; mt++)
#pragma unroll
        for (int nt = 0; nt < 8; nt++)
#pragma unroll
            for (int q = 0; q < 4; q++) acc[mt][nt][q] = 0.f;

    const int mrow0 = lane >> 2;
    const int kcol0 = (lane & 3) * 2;

    mbar_wait(barB + 16, 0);

#pragma unroll 1
    for (int g = 0; g < 16; g++) {
        mbar_wait(barB + (g & 1) * 8, (g >> 1) & 1);

        const float* As = As32 + (g & 1) * STAGE_ELEMS;
        const int kc = g & 7;

#pragma unroll
        for (int ks = 0; ks < 2; ks++) {
            const int kb = ks * 16 + kcol0;
            uint32_t af[2][4];
#pragma unroll
            for (int mt = 0; mt < 2; mt++) {
                int m0 = wm + mt * 16 + mrow0;
                af[mt][0] = pack_bf16x2(As[kb * AS32STR + m0],
                                        As[(kb + 1) * AS32STR + m0]);
                af[mt][1] = pack_bf16x2(As[kb * AS32STR + m0 + 8],
                                        As[(kb + 1) * AS32STR + m0 + 8]);
                af[mt][2] = pack_bf16x2(As[(kb + 8) * AS32STR + m0],
                                        As[(kb + 9) * AS32STR + m0]);
                af[mt][3] = pack_bf16x2(As[(kb + 8) * AS32STR + m0 + 8],
                                        As[(kb + 9) * AS32STR + m0 + 8]);
            }
            uint32_t bf[8][2];
#pragma unroll
            for (int np = 0; np < 4; np++) {
                int n = wn + np * 16 + (lane & 7) + ((lane >> 4) << 3);
                int k = kc * 32 + ks * 16 + ((lane >> 3) & 1) * 8;
                uint32_t r[4];
                ldm_x4(r, bbase + (n * BSTR + k) * 2);
                bf[2 * np][0]     = r[0];  bf[2 * np][1]     = r[1];
                bf[2 * np + 1][0] = r[2];  bf[2 * np + 1][1] = r[3];
            }
#pragma unroll
            for (int mt = 0; mt < 2; mt++)
#pragma unroll
                for (int nt = 0; nt < 8; nt++)
                    mma_bf16(acc[mt][nt], af[mt], bf[nt]);
        }
        __syncthreads();

        if (g + 2 < 16 && tid == 0) {
            const int gn = g + 2;
            const uint32_t bar = barB + (gn & 1) * 8;
            mbar_expect_tx(bar, 16384);
            const float* src = fb + (size_t)((gn & 7) * 32) * HW_ + (gn >> 3) * 128;
            float* dstS = As32 + (gn & 1) * STAGE_ELEMS;
#pragma unroll
            for (int r = 0; r < 32; r++)
                bulk_g2s(s2u(dstS + r * AS32STR), src + (size_t)r * HW_, 512, bar);
        }

        if ((g & 7) == 7) {
            uint8_t* outp = g_vm8 +
                ((size_t)b * HW_ + blockIdx.x * 256 + (g >> 3) * 128) * D_;
#pragma unroll
            for (int mt = 0; mt < 2; mt++) {
#pragma unroll
                for (int nt = 0; nt < 8; nt++) {
                    int r0 = wm + mt * 16 + (lane >> 2);
                    int d0 = wn + nt * 8 + (lane & 3) * 2;
                    *(uint16_t*)&outp[(size_t)r0 * D_ + d0] =
                        pack_e4m3x2(acc[mt][nt][0], acc[mt][nt][1]);
                    *(uint16_t*)&outp[(size_t)(r0 + 8) * D_ + d0] =
                        pack_e4m3x2(acc[mt][nt][2], acc[mt][nt][3]);
                    acc[mt][nt][0] = acc[mt][nt][1] = 0.f;
                    acc[mt][nt][2] = acc[mt][nt][3] = 0.f;
                }
            }
        }
    }
}

// ---------------------------------------------------------------------------
// Kernel 1b: single-pass 3x3 box sum via smem halo tile (R15 form).
// ---------------------------------------------------------------------------
#define BOX_SMEM (6 * 130 * 32 * 4)   // 99840 B

__global__ __launch_bounds__(256) void box_kernel()
{
    extern __shared__ __align__(16) uint32_t bs[];   // [6][130][32]
    const int tid  = threadIdx.x;
    const int lane = tid & 31, warp = tid >> 5;
    const int b      = blockIdx.x >> 5;
    const int y0     = (blockIdx.x & 31) * 4;

    const uint4 z4 = make_uint4(0u, 0u, 0u, 0u);
#pragma unroll 1
    for (int r = 0; r < 6; r++) {
        int y = y0 - 1 + r;
        uint4* dst = (uint4*)(bs + (r * 130 + 1) * 32);
        if ((unsigned)y < 128u) {
            const uint4* src = (const uint4*)(g_vm8 + ((size_t)b * HW_ + y * W_) * D_);
            for (int i = tid; i < 1024; i += 256) dst[i] = src[i];
        } else {
            for (int i = tid; i < 1024; i += 256) dst[i] = z4;
        }
    }
    for (int i = tid; i < 6 * 64; i += 256) {
        int r = i >> 6, c = i & 63;
        int col = (c < 32) ? 0 : 129;
        bs[(r * 130 + col) * 32 + (c & 31)] = 0u;
    }
    __syncthreads();

    uint32_t* outw = (uint32_t*)g_vmB8 + ((size_t)b * HW_ + y0 * W_) * 32 + lane;
#pragma unroll 1
    for (int pp = 0; pp < 64; pp++) {
        int p = warp * 64 + pp;          // 0..511
        int y = p >> 7, x = p & 127;
        __half2 s0 = __float2half2_rn(0.f), s1 = s0;
#pragma unroll
        for (int rr = 0; rr < 3; rr++)
#pragma unroll
            for (int cc = 0; cc < 3; cc++) {
                uint32_t v = bs[((y + rr) * 130 + (x + cc)) * 32 + lane];
                s0 = __hadd2(s0, e4m3x2_to_h2(v & 0xffffu));
                s1 = __hadd2(s1, e4m3x2_to_h2(v >> 16));
            }
        outw[(size_t)(y * W_ + x) * 32] =
            (uint32_t)h2_to_e4m3x2(s0) | ((uint32_t)h2_to_e4m3x2(s1) << 16);
    }
}

// ---------------------------------------------------------------------------
// Kernel 2: standalone 4-tap sampler (bilinear on boxed map) -> g_feat.
// ---------------------------------------------------------------------------
__global__ __launch_bounds__(256, 4) void sample_kernel(const float* __restrict__ coords)
{
    const int tid  = threadIdx.x;
    const int lane = tid & 31, warp = tid >> 5;
    const int ptBase = blockIdx.x * 64 + warp * 8;
    const float inv9 = 1.f / 9.f;

#pragma unroll 1
    for (int i = 0; i < 8; i++) {
        int gpt = ptBase + i;
        int b   = gpt >> 14;

        float cx = coords[2 * gpt], cy = coords[2 * gpt + 1];
        float ix = cx * 127.f, iy = cy * 127.f;
        int x0 = min((int)floorf(ix), 126);
        int y0 = min((int)floorf(iy), 126);
        float fx = ix - (float)x0, fy = iy - (float)y0;
        float w00 = (1.f - fx) * (1.f - fy) * inv9;
        float w10 = fx * (1.f - fy) * inv9;
        float w01 = (1.f - fx) * fy * inv9;
        float w11 = fx * fy * inv9;

        const uint32_t* vmb = ((const uint32_t*)g_vmB8) + (size_t)b * HW_ * 32 + lane;
        uint32_t o00 = (uint32_t)(y0 * W_ + x0) * 32u;
        uint32_t v00 = vmb[o00];
        uint32_t v10 = vmb[o00 + 32];
        uint32_t v01 = vmb[o00 + W_ * 32];
        uint32_t v11 = vmb[o00 + W_ * 32 + 32];

        __half2 a0 = __float2half2_rn(0.f);
        __half2 a1 = a0;
        __half2 h00 = __float2half2_rn(w00), h10 = __float2half2_rn(w10);
        __half2 h01 = __float2half2_rn(w01), h11 = __float2half2_rn(w11);
        a0 = __hfma2(e4m3x2_to_h2(v00 & 0xffffu), h00, a0);
        a1 = __hfma2(e4m3x2_to_h2(v00 >> 16),     h00, a1);
        a0 = __hfma2(e4m3x2_to_h2(v10 & 0xffffu), h10, a0);
        a1 = __hfma2(e4m3x2_to_h2(v10 >> 16),     h10, a1);
        a0 = __hfma2(e4m3x2_to_h2(v01 & 0xffffu), h01, a0);
        a1 = __hfma2(e4m3x2_to_h2(v01 >> 16),     h01, a1);
        a0 = __hfma2(e4m3x2_to_h2(v11 & 0xffffu), h11, a0);
        a1 = __hfma2(e4m3x2_to_h2(v11 >> 16),     h11, a1);

        uint2 pk;
        pk.x = *(uint32_t*)&a0;
        pk.y = *(uint32_t*)&a1;
        *(uint2*)&g_feat[(size_t)gpt * D_ + lane * 4] = pk;
    }
}

// ---------------------------------------------------------------------------
// Kernel 3: MLP GEMM, 2 tiles per block, 2 CTAs/SM. R11 LDGSTS prologue.
// ---------------------------------------------------------------------------
#define FSTR 136
#define TILE_ELEMS (128 * FSTR)
#define MLP_SMEM ((3 * TILE_ELEMS) * 2 + 2 * 128 * 2 * 4)   // 106496 B
#define NTILES 2

__global__ __launch_bounds__(256, 2) void mlp_kernel(
    const float* __restrict__ coords, const float* __restrict__ b1,
    const float* __restrict__ W2,     const float* __restrict__ b2,
    float* __restrict__ out)
{
    extern __shared__ __align__(16) __half smh[];
    __half* W1h = smh;
    __half* Af0 = smh + TILE_ELEMS;
    __half* Af1 = smh + 2 * TILE_ELEMS;
    float*  red = (float*)(smh + 3 * TILE_ELEMS);

    const int tid  = threadIdx.x;
    const int lane = tid & 31, warp = tid >> 5;
    const int wm = (warp & 3) * 32;
    const int wn = (warp >> 2) * 64;
    const size_t tileBase = (size_t)blockIdx.x * NTILES;

    {
#pragma unroll
        for (int i = 0; i < 8; i++) {
            int idx = i * 256 + tid;
            int row = idx >> 4, c8 = (idx & 15) * 8;
            cp_async16(&W1h[row * FSTR + c8], g_w1h + idx * 8);
        }
        const __half* f0 = g_feat + tileBase * 128 * D_;
#pragma unroll
        for (int i = 0; i < 8; i++) {
            int idx = i * 256 + tid;
            int row = idx >> 4, c8 = (idx & 15) * 8;
            cp_async16(&Af0[row * FSTR + c8], f0 + idx * 8);
        }
        asm volatile("cp.async.commit_group;\n" ::: "memory");
        const __half* f1 = f0 + 128 * D_;
#pragma unroll
        for (int i = 0; i < 8; i++) {
            int idx = i * 256 + tid;
            int row = idx >> 4, c8 = (idx & 15) * 8;
            cp_async16(&Af1[row * FSTR + c8], f1 + idx * 8);
        }
        asm volatile("cp.async.commit_group;\n" ::: "memory");
    }

    const uint32_t bbase = s2u(W1h);

#pragma unroll 1
    for (int t = 0; t < NTILES; t++) {
        if (t == 0)
            asm volatile("cp.async.wait_group 1;\n" ::: "memory");
        else
            asm volatile("cp.async.wait_group 0;\n" ::: "memory");
        __syncthreads();

        const int ptBase = (int)(tileBase + t) * 128;
        const uint32_t abase = s2u(t ? Af1 : Af0);

        float acc[2][8][4];
#pragma unroll
        for (int mt = 0; mt < 2; mt++)
#pragma unroll
            for (int nt = 0; nt < 8; nt++)
#pragma unroll
                for (int q = 0; q < 4; q++) acc[mt][nt][q] = 0.f;

#pragma unroll
        for (int kc = 0; kc < 8; kc++) {
            int k0 = kc * 16;
            uint32_t af[2][4];
#pragma unroll
            for (int mt = 0; mt < 2; mt++) {
                int row = wm + mt * 16 + (lane & 15);
                int col = k0 + ((lane >> 4) << 3);
                ldm_x4(af[mt], abase + (row * FSTR + col) * 2);
            }
            uint32_t bf[8][2];
#pragma unroll
            for (int np = 0; np < 4; np++) {
                int n = wn + np * 16 + (lane & 7) + ((lane >> 4) << 3);
                int k = k0 + ((lane >> 3) & 1) * 8;
                uint32_t r[4];
                ldm_x4(r, bbase + (n * FSTR + k) * 2);
                bf[2 * np][0]     = r[0];  bf[2 * np][1]     = r[1];
                bf[2 * np + 1][0] = r[2];  bf[2 * np + 1][1] = r[3];
            }
#pragma unroll
            for (int mt = 0; mt < 2; mt++)
#pragma unroll
                for (int nt = 0; nt < 8; nt++)
                    mma_f16(acc[mt][nt], af[mt], bf[nt]);
        }

        float2 b1v[8], w20v[8], w21v[8];
#pragma unroll
        for (int nt = 0; nt < 8; nt++) {
            int j = wn + nt * 8 + (lane & 3) * 2;
            b1v[nt]  = *(const float2*)&b1[j];
            w20v[nt] = *(const float2*)&W2[j];
            w21v[nt] = *(const float2*)&W2[128 + j];
        }
        float s0[2][2], s1[2][2];
#pragma unroll
        for (int mt = 0; mt < 2; mt++)
#pragma unroll
            for (int hh = 0; hh < 2; hh++) { s0[mt][hh] = 0.f; s1[mt][hh] = 0.f; }
#pragma unroll
        for (int mt = 0; mt < 2; mt++)
#pragma unroll
            for (int nt = 0; nt < 8; nt++) {
                float h00 = fmaxf(acc[mt][nt][0] + b1v[nt].x, 0.f);
                float h01 = fmaxf(acc[mt][nt][1] + b1v[nt].y, 0.f);
                float h10 = fmaxf(acc[mt][nt][2] + b1v[nt].x, 0.f);
                float h11 = fmaxf(acc[mt][nt][3] + b1v[nt].y, 0.f);
                s0[mt][0] = fmaf(w20v[nt].x, h00, s0[mt][0]);
                s0[mt][0] = fmaf(w20v[nt].y, h01, s0[mt][0]);
                s1[mt][0] = fmaf(w21v[nt].x, h00, s1[mt][0]);
                s1[mt][0] = fmaf(w21v[nt].y, h01, s1[mt][0]);
                s0[mt][1] = fmaf(w20v[nt].x, h10, s0[mt][1]);
                s0[mt][1] = fmaf(w20v[nt].y, h11, s0[mt][1]);
                s1[mt][1] = fmaf(w21v[nt].x, h10, s1[mt][1]);
                s1[mt][1] = fmaf(w21v[nt].y, h11, s1[mt][1]);
            }
#pragma unroll
        for (int mt = 0; mt < 2; mt++)
#pragma unroll
            for (int hh = 0; hh < 2; hh++) {
#pragma unroll
                for (int ofs = 1; ofs < 4; ofs <<= 1) {
                    s0[mt][hh] += __shfl_xor_sync(0xffffffffu, s0[mt][hh], ofs);
                    s1[mt][hh] += __shfl_xor_sync(0xffffffffu, s1[mt][hh], ofs);
                }
            }
        if ((lane & 3) == 0) {
            int gg = warp >> 2;
#pragma unroll
            for (int mt = 0; mt < 2; mt++)
#pragma unroll
                for (int hh = 0; hh < 2; hh++) {
                    int row = wm + mt * 16 + (lane >> 2) + 8 * hh;
                    red[(gg * 128 + row) * 2 + 0] = s0[mt][hh];
                    red[(gg * 128 + row) * 2 + 1] = s1[mt][hh];
                }
        }
        __syncthreads();

        {
            int pt = tid >> 1, c = tid & 1;
            float s = b2[c] + red[pt * 2 + c] + red[(128 + pt) * 2 + c];
            float v = tanhf(s) * MAX_DELTA;
            int gi = (ptBase + pt) * 2 + c;
            out[gi] = coords[gi] + v;
        }
        if (t == 0) __syncthreads();
    }
}

// ---------------------------------------------------------------------------
extern "C" void kernel_launch(void* const* d_in, const int* in_sizes, int n_in,
                              void* d_out, int out_size)
{
    (void)in_sizes; (void)n_in; (void)out_size;
    const float* fmap   = (const float*)d_in[0];
    const float* coords = (const float*)d_in[1];
    const float* Wp     = (const float*)d_in[2];
    const float* W1     = (const float*)d_in[3];
    const float* b1     = (const float*)d_in[4];
    const float* W2     = (const float*)d_in[5];
    const float* b2     = (const float*)d_in[6];
    float* out = (float*)d_out;

    wt_convert<<<48, 256>>>(Wp, W1);

    cudaFuncSetAttribute(proj_kernel,
                         cudaFuncAttributeMaxDynamicSharedMemorySize, PROJ_SMEM);
    proj_kernel<<<dim3(HW_ / 256, B_), 256, PROJ_SMEM>>>(fmap);

    cudaFuncSetAttribute(box_kernel,
                         cudaFuncAttributeMaxDynamicSharedMemorySize, BOX_SMEM);
    box_kernel<<<B_ * 32, 256, BOX_SMEM>>>();

    sample_kernel<<<(B_ * T_) / 64, 256>>>(coords);

    cudaFuncSetAttribute(mlp_kernel,
                         cudaFuncAttributeMaxDynamicSharedMemorySize, MLP_SMEM);
    mlp_kernel<<<(B_ * T_) / (128 * NTILES), 256, MLP_SMEM>>>(coords, b1, W2, b2, out);
}

// round 17
// speedup vs baseline: 1.1791x; 1.1791x over previous
#include <cuda_runtime.h>
#include <cuda_bf16.h>
#include <cuda_fp16.h>
#include <math.h>
#include <stdint.h>

#define B_   4
#define C_   256
#define D_   128
#define HW_  16384
#define W_   128
#define T_   16384
#define MAX_DELTA 0.0009765625f   // 0.5/512

__device__ uint8_t g_vm8[(size_t)B_ * HW_ * D_];       // fp8 vm [b][pix][d]
__device__ __half g_feat[(size_t)B_ * T_ * D_];        // fp16 feat [pt][d]
__device__ __half g_w1h[D_ * D_];                      // fp16 W1 [j][k]

// ---------------------------------------------------------------------------
__device__ __forceinline__ uint32_t s2u(const void* p) {
    return (uint32_t)__cvta_generic_to_shared(p);
}
__device__ __forceinline__ void cp_async16(void* smem_dst, const void* gmem_src) {
    asm volatile("cp.async.cg.shared.global [%0], [%1], 16;\n"
        :: "r"(s2u(smem_dst)), "l"(gmem_src));
}
__device__ __forceinline__ void ldm_x4(uint32_t r[4], uint32_t addr) {
    asm volatile("ldmatrix.sync.aligned.m8n8.x4.shared.b16 {%0,%1,%2,%3}, [%4];\n"
        : "=r"(r[0]), "=r"(r[1]), "=r"(r[2]), "=r"(r[3]) : "r"(addr));
}
__device__ __forceinline__ void ldm_x4t(uint32_t r[4], uint32_t addr) {
    asm volatile("ldmatrix.sync.aligned.m8n8.x4.trans.shared.b16 {%0,%1,%2,%3}, [%4];\n"
        : "=r"(r[0]), "=r"(r[1]), "=r"(r[2]), "=r"(r[3]) : "r"(addr));
}
__device__ __forceinline__ void mma_bf16(float c[4], const uint32_t a[4], const uint32_t b[2]) {
    asm volatile("mma.sync.aligned.m16n8k16.row.col.f32.bf16.bf16.f32 "
        "{%0,%1,%2,%3}, {%4,%5,%6,%7}, {%8,%9}, {%0,%1,%2,%3};\n"
        : "+f"(c[0]), "+f"(c[1]), "+f"(c[2]), "+f"(c[3])
        : "r"(a[0]), "r"(a[1]), "r"(a[2]), "r"(a[3]), "r"(b[0]), "r"(b[1]));
}
__device__ __forceinline__ void mma_f16(float c[4], const uint32_t a[4], const uint32_t b[2]) {
    asm volatile("mma.sync.aligned.m16n8k16.row.col.f32.f16.f16.f32 "
        "{%0,%1,%2,%3}, {%4,%5,%6,%7}, {%8,%9}, {%0,%1,%2,%3};\n"
        : "+f"(c[0]), "+f"(c[1]), "+f"(c[2]), "+f"(c[3])
        : "r"(a[0]), "r"(a[1]), "r"(a[2]), "r"(a[3]), "r"(b[0]), "r"(b[1]));
}
__device__ __forceinline__ uint16_t pack_e4m3x2(float lo, float hi) {
    uint16_t r;
    asm("cvt.rn.satfinite.e4m3x2.f32 %0, %1, %2;" : "=h"(r) : "f"(hi), "f"(lo));
    return r;
}
__device__ __forceinline__ __half2 e4m3x2_to_h2(uint32_t u) {
    uint32_t r;
    asm("cvt.rn.f16x2.e4m3x2 %0, %1;" : "=r"(r) : "h"((uint16_t)u));
    return *(__half2*)&r;
}

// smem layout constants for proj
#define ASTR 136
#define BSTR 264
#define BS_ELEMS  (128 * BSTR)
#define AST_ELEMS (32 * ASTR)
#define PROJ_SMEM ((BS_ELEMS + 2 * AST_ELEMS) * 2)   // 84992 bytes

// ---------------------------------------------------------------------------
// Kernel 1: projection GEMM -> fp8 vm. Persistent: 2 m-tiles per block.
// Wp converted fp32->bf16 in-prologue (no separate convert kernel).
// fmap LDG->cvt->STS double-buffered; prefetch chain crosses tiles.
// ---------------------------------------------------------------------------
__global__ __launch_bounds__(256, 2) void proj_kernel(const float* __restrict__ fmap,
                                                      const float* __restrict__ Wp)
{
    extern __shared__ __align__(16) __nv_bfloat16 sm[];
    __nv_bfloat16* Bs  = sm;               // [128 n][BSTR k]
    __nv_bfloat16* AsT = sm + BS_ELEMS;    // [2 buf][32 k][ASTR m]

    const int b    = blockIdx.y;
    const int tid  = threadIdx.x;
    const int lane = tid & 31, warp = tid >> 5;

    // prologue: convert whole Wp fp32 -> bf16 smem (spread over 256 threads)
    for (int i = tid; i < 128 * 256 / 4; i += 256) {
        int idx = i * 4;
        int n = idx >> 8, k = idx & 255;
        float4 v = *(const float4*)&Wp[n * C_ + k];
        __nv_bfloat162* dst = (__nv_bfloat162*)&Bs[n * BSTR + k];
        dst[0] = __floats2bfloat162_rn(v.x, v.y);
        dst[1] = __floats2bfloat162_rn(v.z, v.w);
    }

    const int lk = tid >> 3;
    const int l8 = tid & 7;
    const float* fb = fmap + (size_t)b * C_ * HW_ + blockIdx.x * 256;

    float4 st[4];
#pragma unroll
    for (int j = 0; j < 4; j++)
        st[j] = *(const float4*)&fb[(size_t)lk * HW_ + (l8 + 8 * j) * 4];
    {
        __nv_bfloat16* A0 = AsT;
#pragma unroll
        for (int j = 0; j < 4; j++) {
            int m = (l8 + 8 * j) * 4;
            __nv_bfloat162* d2 = (__nv_bfloat162*)&A0[lk * ASTR + m];
            d2[0] = __floats2bfloat162_rn(st[j].x, st[j].y);
            d2[1] = __floats2bfloat162_rn(st[j].z, st[j].w);
        }
    }
    __syncthreads();

    const int wm = (warp & 3) * 32;
    const int wn = (warp >> 2) * 64;
    const uint32_t bbase = s2u(Bs);

    float acc[2][8][4];
#pragma unroll
    for (int mt = 0; mt < 2; mt++)
#pragma unroll
        for (int nt = 0; nt < 8; nt++)
#pragma unroll
            for (int q = 0; q < 4; q++) acc[mt][nt][q] = 0.f;

#pragma unroll 1
    for (int t = 0; t < 2; t++) {
#pragma unroll 1
        for (int kc = 0; kc < 8; kc++) {
            const int g = t * 8 + kc;
            if (g < 15) {
                const int gn = g + 1;
                const float* src = fb + (size_t)((gn & 7) * 32 + lk) * HW_ + ((gn >> 3) * 128);
#pragma unroll
                for (int j = 0; j < 4; j++)
                    st[j] = *(const float4*)&src[(l8 + 8 * j) * 4];
            }
            const uint32_t abase = s2u(AsT + (g & 1) * AST_ELEMS);

#pragma unroll
            for (int ks = 0; ks < 2; ks++) {
                uint32_t af[2][4];
#pragma unroll
                for (int mt = 0; mt < 2; mt++) {
                    int row = ks * 16 + (lane & 7) + ((lane >> 4) << 3);
                    int col = wm + mt * 16 + ((lane >> 3) & 1) * 8;
                    ldm_x4t(af[mt], abase + (row * ASTR + col) * 2);
                }
                uint32_t bf[8][2];
#pragma unroll
                for (int np = 0; np < 4; np++) {
                    int n = wn + np * 16 + (lane & 7) + ((lane >> 4) << 3);
                    int k = kc * 32 + ks * 16 + ((lane >> 3) & 1) * 8;
                    uint32_t r[4];
                    ldm_x4(r, bbase + (n * BSTR + k) * 2);
                    bf[2 * np][0]     = r[0];  bf[2 * np][1]     = r[1];
                    bf[2 * np + 1][0] = r[2];  bf[2 * np + 1][1] = r[3];
                }
#pragma unroll
                for (int mt = 0; mt < 2; mt++)
#pragma unroll
                    for (int nt = 0; nt < 8; nt++)
                        mma_bf16(acc[mt][nt], af[mt], bf[nt]);
            }

            if (g < 15) {
                __nv_bfloat16* An = AsT + ((g + 1) & 1) * AST_ELEMS;
#pragma unroll
                for (int j = 0; j < 4; j++) {
                    int m = (l8 + 8 * j) * 4;
                    __nv_bfloat162* d2 = (__nv_bfloat162*)&An[lk * ASTR + m];
                    d2[0] = __floats2bfloat162_rn(st[j].x, st[j].y);
                    d2[1] = __floats2bfloat162_rn(st[j].z, st[j].w);
                }
            }
            __syncthreads();
        }

        uint8_t* outp = g_vm8 + ((size_t)b * HW_ + blockIdx.x * 256 + t * 128) * D_;
#pragma unroll
        for (int mt = 0; mt < 2; mt++) {
#pragma unroll
            for (int nt = 0; nt < 8; nt++) {
                int r0 = wm + mt * 16 + (lane >> 2);
                int d0 = wn + nt * 8 + (lane & 3) * 2;
                *(uint16_t*)&outp[(size_t)r0 * D_ + d0] =
                    pack_e4m3x2(acc[mt][nt][0], acc[mt][nt][1]);
                *(uint16_t*)&outp[(size_t)(r0 + 8) * D_ + d0] =
                    pack_e4m3x2(acc[mt][nt][2], acc[mt][nt][3]);
                acc[mt][nt][0] = acc[mt][nt][1] = acc[mt][nt][2] = acc[mt][nt][3] = 0.f;
            }
        }
    }
}

// ---------------------------------------------------------------------------
// Kernel 2: branch-free 16-tap stencil sampler (R9 form). Extra blocks
// (>= NSAMP_BLKS) convert W1 fp32 -> fp16 g_w1h for the mlp kernel.
// ---------------------------------------------------------------------------
#define NSAMP_BLKS ((B_ * T_) / 64)   // 1024

__global__ __launch_bounds__(256, 4) void sample_kernel(const float* __restrict__ coords,
                                                        const float* __restrict__ W1)
{
    const int tid  = threadIdx.x;

    if (blockIdx.x >= NSAMP_BLKS) {
        int i = (blockIdx.x - NSAMP_BLKS) * 256 + tid;   // < 4096 float4s
        float4 v = *(const float4*)&W1[i * 4];
        __half2* dst = (__half2*)&g_w1h[i * 4];
        dst[0] = __floats2half2_rn(v.x, v.y);
        dst[1] = __floats2half2_rn(v.z, v.w);
        return;
    }

    const int lane = tid & 31, warp = tid >> 5;
    const int ptBase = blockIdx.x * 64 + warp * 8;
    const float inv9 = 1.f / 9.f;

#pragma unroll 1
    for (int i = 0; i < 8; i++) {
        int gpt = ptBase + i;
        int b   = gpt >> 14;

        float cx = coords[2 * gpt], cy = coords[2 * gpt + 1];
        float ix = cx * 127.f, iy = cy * 127.f;
        float xf = floorf(ix), yf = floorf(iy);
        int   x0 = (int)xf,    y0 = (int)yf;
        float fx = ix - xf,    fy = iy - yf;
        float Xw[4] = {1.f - fx, 1.f, 1.f, fx};
        float Yw[4] = {1.f - fy, 1.f, 1.f, fy};

        float wx[4], wy[4];
        int   px[4], py[4];
#pragma unroll
        for (int q = 0; q < 4; q++) {
            int x = x0 - 1 + q;
            bool vx = ((unsigned)x < 128u);
            wx[q] = vx ? Xw[q] : 0.f;
            px[q] = vx ? x : 0;
            int y = y0 - 1 + q;
            bool vy = ((unsigned)y < 128u);
            wy[q] = vy ? (Yw[q] * inv9) : 0.f;
            py[q] = vy ? y : 0;
        }

        const uint32_t* vmb = ((const uint32_t*)g_vm8) + (size_t)b * HW_ * 32 + lane;
        uint32_t off[16];
#pragma unroll
        for (int j = 0; j < 4; j++)
#pragma unroll
            for (int q = 0; q < 4; q++)
                off[j * 4 + q] = (uint32_t)(py[j] * W_ + px[q]) * 32u;

        uint32_t v[16];
#pragma unroll
        for (int t = 0; t < 16; t++) v[t] = vmb[off[t]];

        __half2 a01 = __float2half2_rn(0.f);
        __half2 a23 = a01;
#pragma unroll
        for (int j = 0; j < 4; j++)
#pragma unroll
            for (int q = 0; q < 4; q++) {
                int t = j * 4 + q;
                __half2 w2 = __float2half2_rn(wy[j] * wx[q]);
                a01 = __hfma2(e4m3x2_to_h2(v[t] & 0xffffu), w2, a01);
                a23 = __hfma2(e4m3x2_to_h2(v[t] >> 16), w2, a23);
            }

        uint2 pk;
        pk.x = *(uint32_t*)&a01;
        pk.y = *(uint32_t*)&a23;
        *(uint2*)&g_feat[(size_t)gpt * D_ + lane * 4] = pk;
    }
}

// ---------------------------------------------------------------------------
// Kernel 3: MLP GEMM, 2 tiles per block, 2 CTAs/SM (R9 exact).
// ---------------------------------------------------------------------------
#define FSTR 136
#define TILE_ELEMS (128 * FSTR)
#define MLP_SMEM ((3 * TILE_ELEMS) * 2 + 2 * 128 * 2 * 4)   // 106496 B
#define NTILES 2

__global__ __launch_bounds__(256, 2) void mlp_kernel(
    const float* __restrict__ coords, const float* __restrict__ b1,
    const float* __restrict__ W2,     const float* __restrict__ b2,
    float* __restrict__ out)
{
    extern __shared__ __align__(16) __half smh[];
    __half* W1h = smh;
    __half* Af0 = smh + TILE_ELEMS;
    __half* Af1 = smh + 2 * TILE_ELEMS;
    float*  red = (float*)(smh + 3 * TILE_ELEMS);

    const int tid  = threadIdx.x;
    const int lane = tid & 31, warp = tid >> 5;
    const int wm = (warp & 3) * 32;
    const int wn = (warp >> 2) * 64;
    const size_t tileBase = (size_t)blockIdx.x * NTILES;

    {
#pragma unroll
        for (int i = 0; i < 8; i++) {
            int idx = i * 256 + tid;
            int row = idx >> 4, c8 = (idx & 15) * 8;
            cp_async16(&W1h[row * FSTR + c8], g_w1h + idx * 8);
        }
        const __half* f0 = g_feat + tileBase * 128 * D_;
#pragma unroll
        for (int i = 0; i < 8; i++) {
            int idx = i * 256 + tid;
            int row = idx >> 4, c8 = (idx & 15) * 8;
            cp_async16(&Af0[row * FSTR + c8], f0 + idx * 8);
        }
        asm volatile("cp.async.commit_group;\n" ::: "memory");
        const __half* f1 = f0 + 128 * D_;
#pragma unroll
        for (int i = 0; i < 8; i++) {
            int idx = i * 256 + tid;
            int row = idx >> 4, c8 = (idx & 15) * 8;
            cp_async16(&Af1[row * FSTR + c8], f1 + idx * 8);
        }
        asm volatile("cp.async.commit_group;\n" ::: "memory");
    }

    const uint32_t bbase = s2u(W1h);

#pragma unroll 1
    for (int t = 0; t < NTILES; t++) {
        if (t == 0)
            asm volatile("cp.async.wait_group 1;\n" ::: "memory");
        else
            asm volatile("cp.async.wait_group 0;\n" ::: "memory");
        __syncthreads();

        const int ptBase = (int)(tileBase + t) * 128;
        const uint32_t abase = s2u(t ? Af1 : Af0);

        float acc[2][8][4];
#pragma unroll
        for (int mt = 0; mt < 2; mt++)
#pragma unroll
            for (int nt = 0; nt < 8; nt++)
#pragma unroll
                for (int q = 0; q < 4; q++) acc[mt][nt][q] = 0.f;

#pragma unroll
        for (int kc = 0; kc < 8; kc++) {
            int k0 = kc * 16;
            uint32_t af[2][4];
#pragma unroll
            for (int mt = 0; mt < 2; mt++) {
                int row = wm + mt * 16 + (lane & 15);
                int col = k0 + ((lane >> 4) << 3);
                ldm_x4(af[mt], abase + (row * FSTR + col) * 2);
            }
            uint32_t bf[8][2];
#pragma unroll
            for (int np = 0; np < 4; np++) {
                int n = wn + np * 16 + (lane & 7) + ((lane >> 4) << 3);
                int k = k0 + ((lane >> 3) & 1) * 8;
                uint32_t r[4];
                ldm_x4(r, bbase + (n * FSTR + k) * 2);
                bf[2 * np][0]     = r[0];  bf[2 * np][1]     = r[1];
                bf[2 * np + 1][0] = r[2];  bf[2 * np + 1][1] = r[3];
            }
#pragma unroll
            for (int mt = 0; mt < 2; mt++)
#pragma unroll
                for (int nt = 0; nt < 8; nt++)
                    mma_f16(acc[mt][nt], af[mt], bf[nt]);
        }

        float2 b1v[8], w20v[8], w21v[8];
#pragma unroll
        for (int nt = 0; nt < 8; nt++) {
            int j = wn + nt * 8 + (lane & 3) * 2;
            b1v[nt]  = *(const float2*)&b1[j];
            w20v[nt] = *(const float2*)&W2[j];
            w21v[nt] = *(const float2*)&W2[128 + j];
        }
        float s0[2][2], s1[2][2];
#pragma unroll
        for (int mt = 0; mt < 2; mt++)
#pragma unroll
            for (int hh = 0; hh < 2; hh++) { s0[mt][hh] = 0.f; s1[mt][hh] = 0.f; }
#pragma unroll
        for (int mt = 0; mt < 2; mt++)
#pragma unroll
            for (int nt = 0; nt < 8; nt++) {
                float h00 = fmaxf(acc[mt][nt][0] + b1v[nt].x, 0.f);
                float h01 = fmaxf(acc[mt][nt][1] + b1v[nt].y, 0.f);
                float h10 = fmaxf(acc[mt][nt][2] + b1v[nt].x, 0.f);
                float h11 = fmaxf(acc[mt][nt][3] + b1v[nt].y, 0.f);
                s0[mt][0] = fmaf(w20v[nt].x, h00, s0[mt][0]);
                s0[mt][0] = fmaf(w20v[nt].y, h01, s0[mt][0]);
                s1[mt][0] = fmaf(w21v[nt].x, h00, s1[mt][0]);
                s1[mt][0] = fmaf(w21v[nt].y, h01, s1[mt][0]);
                s0[mt][1] = fmaf(w20v[nt].x, h10, s0[mt][1]);
                s0[mt][1] = fmaf(w20v[nt].y, h11, s0[mt][1]);
                s1[mt][1] = fmaf(w21v[nt].x, h10, s1[mt][1]);
                s1[mt][1] = fmaf(w21v[nt].y, h11, s1[mt][1]);
            }
#pragma unroll
        for (int mt = 0; mt < 2; mt++)
#pragma unroll
            for (int hh = 0; hh < 2; hh++) {
#pragma unroll
                for (int ofs = 1; ofs < 4; ofs <<= 1) {
                    s0[mt][hh] += __shfl_xor_sync(0xffffffffu, s0[mt][hh], ofs);
                    s1[mt][hh] += __shfl_xor_sync(0xffffffffu, s1[mt][hh], ofs);
                }
            }
        if ((lane & 3) == 0) {
            int gg = warp >> 2;
#pragma unroll
            for (int mt = 0; mt < 2; mt++)
#pragma unroll
                for (int hh = 0; hh < 2; hh++) {
                    int row = wm + mt * 16 + (lane >> 2) + 8 * hh;
                    red[(gg * 128 + row) * 2 + 0] = s0[mt][hh];
                    red[(gg * 128 + row) * 2 + 1] = s1[mt][hh];
                }
        }
        __syncthreads();

        {
            int pt = tid >> 1, c = tid & 1;
            float s = b2[c] + red[pt * 2 + c] + red[(128 + pt) * 2 + c];
            float v = tanhf(s) * MAX_DELTA;
            int gi = (ptBase + pt) * 2 + c;
            out[gi] = coords[gi] + v;
        }
        if (t == 0) __syncthreads();
    }
}

// ---------------------------------------------------------------------------
extern "C" void kernel_launch(void* const* d_in, const int* in_sizes, int n_in,
                              void* d_out, int out_size)
{
    (void)in_sizes; (void)n_in; (void)out_size;
    const float* fmap   = (const float*)d_in[0];
    const float* coords = (const float*)d_in[1];
    const float* Wp     = (const float*)d_in[2];
    const float* W1     = (const float*)d_in[3];
    const float* b1     = (const float*)d_in[4];
    const float* W2     = (const float*)d_in[5];
    const float* b2     = (const float*)d_in[6];
    float* out = (float*)d_out;

    cudaFuncSetAttribute(proj_kernel,
                         cudaFuncAttributeMaxDynamicSharedMemorySize, PROJ_SMEM);
    proj_kernel<<<dim3(HW_ / 256, B_), 256, PROJ_SMEM>>>(fmap, Wp);

    sample_kernel<<<NSAMP_BLKS + 16, 256>>>(coords, W1);

    cudaFuncSetAttribute(mlp_kernel,
                         cudaFuncAttributeMaxDynamicSharedMemorySize, MLP_SMEM);
    mlp_kernel<<<(B_ * T_) / (128 * NTILES), 256, MLP_SMEM>>>(coords, b1, W2, b2, out);
}